// round 5
// baseline (speedup 1.0000x reference)
#include <cuda_runtime.h>

// RNNModel: x[8192,512,8] fp32 -> out[8192] fp32.
// R4: 4 lanes per batch element (1024 warps -> 2 warps/SMSP on 128 SMs).
// Accumulators/weights held as b64 registers; fma.rn.f32x2 issued with "l"
// constraints so NO pack/unpack movs sit in the dependency chain.
// Weights pre-scaled by 2*log2(e); tanh = 1 - 2/(ex2(a)+1).

constexpr int T_LEN = 512;
constexpr int I_LEN = 8;
constexpr int H_LEN = 16;

typedef unsigned long long ull;

__device__ __forceinline__ ull ffma2(ull a, ull b, ull c) {
    ull d;
    asm("fma.rn.f32x2 %0, %1, %2, %3;" : "=l"(d) : "l"(a), "l"(b), "l"(c));
    return d;
}
__device__ __forceinline__ ull dup2(float v) {
    ull d;
    asm("mov.b64 %0, {%1, %1};" : "=l"(d) : "f"(v));
    return d;
}
__device__ __forceinline__ ull pack2(float x, float y) {
    ull d;
    asm("mov.b64 %0, {%1, %2};" : "=l"(d) : "f"(x), "f"(y));
    return d;
}
__device__ __forceinline__ void unpack2(ull d, float& x, float& y) {
    asm("mov.b64 {%0, %1}, %2;" : "=f"(x), "=f"(y) : "l"(d));
}

// v pre-scaled by 2*log2(e): tanh = 1 - 2/(ex2(v)+1). ~1e-7 abs err.
__device__ __forceinline__ float tanh_pre(float v) {
    float e, r;
    asm("ex2.approx.f32 %0, %1;" : "=f"(e) : "f"(v));
    asm("rcp.approx.f32 %0, %1;" : "=f"(r) : "f"(e + 1.0f));
    return fmaf(-2.0f, r, 1.0f);
}

__global__ void __launch_bounds__(256) rnn_fused4_kernel(
    const float* __restrict__ x,
    const float* __restrict__ W_ih,
    const float* __restrict__ W_hh,
    const float* __restrict__ b_ih,
    const float* __restrict__ b_hh,
    const float* __restrict__ fc_w,
    const float* __restrict__ fc_b,
    float* __restrict__ out,
    int n_batch)
{
    const int tid = blockIdx.x * blockDim.x + threadIdx.x;
    const int sub = tid & 3;        // lane within 4-lane group
    const int b   = tid >> 2;       // batch element
    if (b >= n_batch) return;
    const int c0 = sub * 4;         // own channel base

    const float C = 2.8853900817779268f;  // 2*log2(e), folded into weights

    // w[p][m][k]: W_hh column (channel 4*(sub^m)+k) for output pair p
    // (outputs c0+2p, c0+2p+1). m=0 -> own h, m=1..3 -> shfl_xor(m) partner h.
    ull w[2][4][4];
#pragma unroll
    for (int p = 0; p < 2; p++) {
        const int r0 = (c0 + 2 * p) * H_LEN;
        const int r1 = r0 + H_LEN;
#pragma unroll
        for (int m = 0; m < 4; m++) {
            const int cb = 4 * (sub ^ m);
#pragma unroll
            for (int k = 0; k < 4; k++)
                w[p][m][k] = pack2(C * W_hh[r0 + cb + k], C * W_hh[r1 + cb + k]);
        }
    }
    ull u[2][I_LEN];
#pragma unroll
    for (int p = 0; p < 2; p++) {
        const int r0 = (c0 + 2 * p) * I_LEN;
        const int r1 = r0 + I_LEN;
#pragma unroll
        for (int i = 0; i < I_LEN; i++)
            u[p][i] = pack2(C * W_ih[r0 + i], C * W_ih[r1 + i]);
    }
    ull bias[2];
#pragma unroll
    for (int p = 0; p < 2; p++)
        bias[p] = pack2(C * (b_ih[c0 + 2 * p]     + b_hh[c0 + 2 * p]),
                        C * (b_ih[c0 + 2 * p + 1] + b_hh[c0 + 2 * p + 1]));

    float hs[4] = {0.f, 0.f, 0.f, 0.f};   // own 4 hidden channels

    const float4* xb = reinterpret_cast<const float4*>(x + (size_t)b * T_LEN * I_LEN);

    // Input projection of one timestep into fresh b64 accumulators.
    auto proj = [&](ull* a, float4 q0, float4 q1) {
        a[0] = bias[0];
        a[1] = bias[1];
        const float xs[8] = {q0.x, q0.y, q0.z, q0.w, q1.x, q1.y, q1.z, q1.w};
#pragma unroll
        for (int i = 0; i < I_LEN; i++) {
            const ull d = dup2(xs[i]);
            a[0] = ffma2(d, u[0][i], a[0]);
            a[1] = ffma2(d, u[1][i], a[1]);
        }
    };

    // Recurrent part: shuffles first (26-cyc latency covered by caller's
    // next-step proj), then 32 chained FMA2s, then tanh.
    auto recur = [&](ull* ip) {
        float rv[3][4];
#pragma unroll
        for (int m = 1; m < 4; m++)
#pragma unroll
            for (int k = 0; k < 4; k++)
                rv[m - 1][k] = __shfl_xor_sync(0xffffffffu, hs[k], m);

#pragma unroll
        for (int k = 0; k < 4; k++) {           // own h
            const ull d = dup2(hs[k]);
            ip[0] = ffma2(d, w[0][0][k], ip[0]);
            ip[1] = ffma2(d, w[1][0][k], ip[1]);
        }
#pragma unroll
        for (int m = 1; m < 4; m++)             // partner h
#pragma unroll
            for (int k = 0; k < 4; k++) {
                const ull d = dup2(rv[m - 1][k]);
                ip[0] = ffma2(d, w[0][m][k], ip[0]);
                ip[1] = ffma2(d, w[1][m][k], ip[1]);
            }

        float a0, a1, a2, a3;
        unpack2(ip[0], a0, a1);
        unpack2(ip[1], a2, a3);
        hs[0] = tanh_pre(a0);
        hs[1] = tanh_pre(a1);
        hs[2] = tanh_pre(a2);
        hs[3] = tanh_pre(a3);
    };

    // Pipeline: ip = input projection of step t; compute step t+1's proj
    // while step t's shfl/FMA/tanh chain is in flight.
    float4 p0 = xb[0];
    float4 p1 = xb[1];
    ull ip[2];
    proj(ip, p0, p1);

    for (int t = 0; t < T_LEN - 1; t++) {
        float4 n0 = xb[2 * (t + 1) + 0];
        float4 n1 = xb[2 * (t + 1) + 1];
        ull ipn[2];
        proj(ipn, n0, n1);
        recur(ip);
        ip[0] = ipn[0];
        ip[1] = ipn[1];
    }
    recur(ip);

    // fc over own 4 channels, butterfly-reduce across the 4-lane group.
    float part = hs[0] * fc_w[c0 + 0] + hs[1] * fc_w[c0 + 1]
               + hs[2] * fc_w[c0 + 2] + hs[3] * fc_w[c0 + 3];
    part += __shfl_xor_sync(0xffffffffu, part, 1);
    part += __shfl_xor_sync(0xffffffffu, part, 2);
    if (sub == 0) out[b] = part + fc_b[0];
}

extern "C" void kernel_launch(void* const* d_in, const int* in_sizes, int n_in,
                              void* d_out, int out_size)
{
    const float* x    = (const float*)d_in[0];
    const float* W_ih = (const float*)d_in[1];
    const float* W_hh = (const float*)d_in[2];
    const float* b_ih = (const float*)d_in[3];
    const float* b_hh = (const float*)d_in[4];
    const float* fc_w = (const float*)d_in[5];
    const float* fc_b = (const float*)d_in[6];
    float* out = (float*)d_out;

    const int n_batch = out_size;        // 8192
    const int threads = n_batch * 4;     // 32768
    const int block   = 256;             // 8 warps -> 2 per SMSP
    const int grid    = (threads + block - 1) / block;   // 128
    rnn_fused4_kernel<<<grid, block>>>(x, W_ih, W_hh, b_ih, b_hh, fc_w, fc_b,
                                       out, n_batch);
}

// round 6
// speedup vs baseline: 1.3445x; 1.3445x over previous
#include <cuda_runtime.h>

// RNNModel: x[8192,512,8] fp32 -> out[8192] fp32.
// R5: R4 compute core (4 lanes/batch, b64 fma.rn.f32x2, pre-scaled weights)
// + deep x prefetch: 4-step chunks, double-buffered -> 8 LDG.128 in flight
// per thread (MLP 2 -> 8) to lift the memory-latency wall (~732 GB/s seen).

constexpr int T_LEN = 512;
constexpr int I_LEN = 8;
constexpr int H_LEN = 16;
constexpr int CHUNK = 4;                    // steps per buffer
constexpr int NCHUNK = T_LEN / CHUNK;       // 128

typedef unsigned long long ull;

__device__ __forceinline__ ull ffma2(ull a, ull b, ull c) {
    ull d;
    asm("fma.rn.f32x2 %0, %1, %2, %3;" : "=l"(d) : "l"(a), "l"(b), "l"(c));
    return d;
}
__device__ __forceinline__ ull dup2(float v) {
    ull d;
    asm("mov.b64 %0, {%1, %1};" : "=l"(d) : "f"(v));
    return d;
}
__device__ __forceinline__ ull pack2(float x, float y) {
    ull d;
    asm("mov.b64 %0, {%1, %2};" : "=l"(d) : "f"(x), "f"(y));
    return d;
}
__device__ __forceinline__ void unpack2(ull d, float& x, float& y) {
    asm("mov.b64 {%0, %1}, %2;" : "=f"(x), "=f"(y) : "l"(d));
}

// v pre-scaled by 2*log2(e): tanh = 1 - 2/(ex2(v)+1). ~1e-7 abs err.
__device__ __forceinline__ float tanh_pre(float v) {
    float e, r;
    asm("ex2.approx.f32 %0, %1;" : "=f"(e) : "f"(v));
    asm("rcp.approx.f32 %0, %1;" : "=f"(r) : "f"(e + 1.0f));
    return fmaf(-2.0f, r, 1.0f);
}

__global__ void __launch_bounds__(256) rnn_fused5_kernel(
    const float* __restrict__ x,
    const float* __restrict__ W_ih,
    const float* __restrict__ W_hh,
    const float* __restrict__ b_ih,
    const float* __restrict__ b_hh,
    const float* __restrict__ fc_w,
    const float* __restrict__ fc_b,
    float* __restrict__ out,
    int n_batch)
{
    const int tid = blockIdx.x * blockDim.x + threadIdx.x;
    const int sub = tid & 3;        // lane within 4-lane group
    const int b   = tid >> 2;       // batch element
    if (b >= n_batch) return;
    const int c0 = sub * 4;         // own channel base

    const float C = 2.8853900817779268f;  // 2*log2(e) folded into weights

    // w[p][m][k]: scaled W_hh column (channel 4*(sub^m)+k) for output pair p.
    ull w[2][4][4];
#pragma unroll
    for (int p = 0; p < 2; p++) {
        const int r0 = (c0 + 2 * p) * H_LEN;
        const int r1 = r0 + H_LEN;
#pragma unroll
        for (int m = 0; m < 4; m++) {
            const int cb = 4 * (sub ^ m);
#pragma unroll
            for (int k = 0; k < 4; k++)
                w[p][m][k] = pack2(C * W_hh[r0 + cb + k], C * W_hh[r1 + cb + k]);
        }
    }
    ull u[2][I_LEN];
#pragma unroll
    for (int p = 0; p < 2; p++) {
        const int r0 = (c0 + 2 * p) * I_LEN;
        const int r1 = r0 + I_LEN;
#pragma unroll
        for (int i = 0; i < I_LEN; i++)
            u[p][i] = pack2(C * W_ih[r0 + i], C * W_ih[r1 + i]);
    }
    ull bias[2];
#pragma unroll
    for (int p = 0; p < 2; p++)
        bias[p] = pack2(C * (b_ih[c0 + 2 * p]     + b_hh[c0 + 2 * p]),
                        C * (b_ih[c0 + 2 * p + 1] + b_hh[c0 + 2 * p + 1]));

    float hs[4] = {0.f, 0.f, 0.f, 0.f};

    const float4* xb = reinterpret_cast<const float4*>(x + (size_t)b * T_LEN * I_LEN);

    // One full step from two float4s of x.
    auto step = [&](float4 q0, float4 q1) {
        // input projection (independent of h; scheduler hoists under shfl/tanh)
        ull a0 = bias[0], a1 = bias[1];
        const float xs[8] = {q0.x, q0.y, q0.z, q0.w, q1.x, q1.y, q1.z, q1.w};
#pragma unroll
        for (int i = 0; i < I_LEN; i++) {
            const ull d = dup2(xs[i]);
            a0 = ffma2(d, u[0][i], a0);
            a1 = ffma2(d, u[1][i], a1);
        }
        // gather partner h
        float rv[3][4];
#pragma unroll
        for (int m = 1; m < 4; m++)
#pragma unroll
            for (int k = 0; k < 4; k++)
                rv[m - 1][k] = __shfl_xor_sync(0xffffffffu, hs[k], m);
        // recurrent matmul
#pragma unroll
        for (int k = 0; k < 4; k++) {
            const ull d = dup2(hs[k]);
            a0 = ffma2(d, w[0][0][k], a0);
            a1 = ffma2(d, w[1][0][k], a1);
        }
#pragma unroll
        for (int m = 1; m < 4; m++)
#pragma unroll
            for (int k = 0; k < 4; k++) {
                const ull d = dup2(rv[m - 1][k]);
                a0 = ffma2(d, w[0][m][k], a0);
                a1 = ffma2(d, w[1][m][k], a1);
            }
        float v0, v1, v2, v3;
        unpack2(a0, v0, v1);
        unpack2(a1, v2, v3);
        hs[0] = tanh_pre(v0);
        hs[1] = tanh_pre(v1);
        hs[2] = tanh_pre(v2);
        hs[3] = tanh_pre(v3);
    };

    // Double-buffered 4-step chunks: 8 LDG.128 outstanding while computing.
    float4 A[2 * CHUNK], B[2 * CHUNK];
#pragma unroll
    for (int i = 0; i < 2 * CHUNK; i++) A[i] = __ldg(&xb[i]);

    for (int c = 0; c < NCHUNK; c += 2) {
        // prefetch chunk c+1 (always exists: NCHUNK even)
        const float4* pB = xb + (size_t)(c + 1) * 2 * CHUNK;
#pragma unroll
        for (int i = 0; i < 2 * CHUNK; i++) B[i] = __ldg(&pB[i]);
#pragma unroll
        for (int s = 0; s < CHUNK; s++) step(A[2 * s], A[2 * s + 1]);

        if (c + 2 < NCHUNK) {
            const float4* pA = xb + (size_t)(c + 2) * 2 * CHUNK;
#pragma unroll
            for (int i = 0; i < 2 * CHUNK; i++) A[i] = __ldg(&pA[i]);
        }
#pragma unroll
        for (int s = 0; s < CHUNK; s++) step(B[2 * s], B[2 * s + 1]);
    }

    // fc over own 4 channels, butterfly-reduce across the group.
    float part = hs[0] * fc_w[c0 + 0] + hs[1] * fc_w[c0 + 1]
               + hs[2] * fc_w[c0 + 2] + hs[3] * fc_w[c0 + 3];
    part += __shfl_xor_sync(0xffffffffu, part, 1);
    part += __shfl_xor_sync(0xffffffffu, part, 2);
    if (sub == 0) out[b] = part + fc_b[0];
}

extern "C" void kernel_launch(void* const* d_in, const int* in_sizes, int n_in,
                              void* d_out, int out_size)
{
    const float* x    = (const float*)d_in[0];
    const float* W_ih = (const float*)d_in[1];
    const float* W_hh = (const float*)d_in[2];
    const float* b_ih = (const float*)d_in[3];
    const float* b_hh = (const float*)d_in[4];
    const float* fc_w = (const float*)d_in[5];
    const float* fc_b = (const float*)d_in[6];
    float* out = (float*)d_out;

    const int n_batch = out_size;        // 8192
    const int threads = n_batch * 4;     // 32768
    const int block   = 256;             // 8 warps -> 2 per SMSP
    const int grid    = (threads + block - 1) / block;   // 128
    rnn_fused5_kernel<<<grid, block>>>(x, W_ih, W_hh, b_ih, b_hh, fc_w, fc_b,
                                       out, n_batch);
}